// round 3
// baseline (speedup 1.0000x reference)
#include <cuda_runtime.h>
#include <math.h>

// Problem constants (fixed shapes per reference setup_inputs)
#define N_TOK 1024
#define TOPK  2
#define NP    (N_TOK * TOPK)   // 2048 (token, k) pairs
#define NE    16
#define HID   1024
#define TWO_H 2048
#define DM    2048
#define RR    16
#define LSCALE 0.25f

// -------- device scratch (static; no allocations allowed) --------
__device__ int   g_perm[NP];              // pair ids grouped by expert
__device__ int   g_offs[NE + 1];          // per-expert offsets into g_perm
__device__ float g_tup[NP * RR];          // lora-A up:    x @ up_a^T
__device__ float g_act[(size_t)NP * HID]; // activations   [pair][H]
__device__ float g_tdn[NP * RR];          // lora-A down:  act @ down_a^T
__device__ float g_buf[(size_t)NP * DM];  // per-pair down output

// ================= routing: group pairs by expert =================
__global__ void route_kernel(const int* __restrict__ ids) {
    __shared__ int cnt[NE];
    __shared__ int base[NE + 1];
    __shared__ int cur[NE];
    int t = threadIdx.x;
    if (t < NE) cnt[t] = 0;
    __syncthreads();
    for (int p = t; p < NP; p += blockDim.x) atomicAdd(&cnt[ids[p]], 1);
    __syncthreads();
    if (t == 0) {
        int s = 0;
        for (int e = 0; e < NE; e++) { base[e] = s; s += cnt[e]; }
        base[NE] = s;
    }
    __syncthreads();
    if (t <= NE) g_offs[t] = base[t];
    if (t < NE)  cur[t] = base[t];
    __syncthreads();
    for (int p = t; p < NP; p += blockDim.x) {
        int pos = atomicAdd(&cur[ids[p]], 1);
        g_perm[pos] = p;   // order within expert is irrelevant (per-pair results independent)
    }
}

// ================= lora-A up: t_up[p][r] = x[n] . up_a[e][r] =================
__global__ void tup_kernel(const float* __restrict__ x,
                           const float* __restrict__ up_a,
                           const int*   __restrict__ ids) {
    int p = blockIdx.x;
    int e = ids[p];
    const float4* xr = (const float4*)(x + (size_t)(p >> 1) * DM);
    int w = threadIdx.x >> 5, lane = threadIdx.x & 31;
    for (int r = w; r < RR; r += 4) {
        const float4* ar = (const float4*)(up_a + ((size_t)e * RR + r) * DM);
        float s = 0.f;
        for (int d = lane; d < DM / 4; d += 32) {
            float4 xv = xr[d], av = ar[d];
            s = fmaf(xv.x, av.x, s);
            s = fmaf(xv.y, av.y, s);
            s = fmaf(xv.z, av.z, s);
            s = fmaf(xv.w, av.w, s);
        }
        #pragma unroll
        for (int o = 16; o; o >>= 1) s += __shfl_xor_sync(0xffffffffu, s, o);
        if (lane == 0) g_tup[p * RR + r] = s;
    }
}

// ================= lora-A down: t_dn[p][r] = act[p] . down_a[e][r] =================
__global__ void tdn_kernel(const float* __restrict__ down_a,
                           const int*   __restrict__ ids) {
    int p = blockIdx.x;
    int e = ids[p];
    const float4* xr = (const float4*)(g_act + (size_t)p * HID);
    int w = threadIdx.x >> 5, lane = threadIdx.x & 31;
    for (int r = w; r < RR; r += 4) {
        const float4* ar = (const float4*)(down_a + ((size_t)e * RR + r) * HID);
        float s = 0.f;
        for (int d = lane; d < HID / 4; d += 32) {
            float4 xv = xr[d], av = ar[d];
            s = fmaf(xv.x, av.x, s);
            s = fmaf(xv.y, av.y, s);
            s = fmaf(xv.z, av.z, s);
            s = fmaf(xv.w, av.w, s);
        }
        #pragma unroll
        for (int o = 16; o; o >>= 1) s += __shfl_xor_sync(0xffffffffu, s, o);
        if (lane == 0) g_tdn[p * RR + r] = s;
    }
}

// ================= up GEMM + lora-B + erf-gelu-mul =================
// Grouped GEMM per expert. BM=64 rows (pairs), BN=64 cols = 32 (gate,up) column
// pairs interleaved so each thread owns matching gate/up columns and can apply
// the activation locally. BK=16, 128 threads, 8x4 per-thread tile.
__global__ __launch_bounds__(128) void up_kernel(const float* __restrict__ x,
                                                 const float* __restrict__ w_up,
                                                 const float* __restrict__ up_b) {
    int e   = blockIdx.z;
    int off = g_offs[e];
    int Me  = g_offs[e + 1] - off;
    int m0  = blockIdx.y * 64;
    if (m0 >= Me) return;
    int g0 = blockIdx.x * 32;  // gate-column base within [0, H)

    __shared__ float As[16][68];
    __shared__ float Bs[16][68];
    __shared__ float Ts[64][16];   // t_up tile
    __shared__ float Ub[64][17];   // up_b tile (padded vs bank conflicts)
    __shared__ int   Pr[64];       // pair id per row
    __shared__ int   Rw[64];       // token id per row

    int tid = threadIdx.x;
    if (tid < 64) {
        int mm = m0 + tid;
        int p  = g_perm[off + min(mm, Me - 1)];   // clamp ragged tail
        Pr[tid] = p;
        Rw[tid] = p >> 1;
    }
    __syncthreads();
    for (int i = tid; i < 64 * 16; i += 128) {
        int m = i >> 4, r = i & 15;
        Ts[m][r] = g_tup[Pr[m] * RR + r];
    }
    for (int i = tid; i < 64 * 16; i += 128) {
        int nn = i >> 4, r = i & 15;
        int col = (nn & 1) ? (HID + g0 + (nn >> 1)) : (g0 + (nn >> 1));
        Ub[nn][r] = up_b[((size_t)e * TWO_H + col) * RR + r];
    }

    int tx = tid & 15, ty = tid >> 4;   // tx: 16 col groups, ty: 8 row groups
    float acc[8][4];
    #pragma unroll
    for (int i = 0; i < 8; i++)
        #pragma unroll
        for (int j = 0; j < 4; j++) acc[i][j] = 0.f;

    int ld_d = tid & 15;   // k within tile
    int ld_r = tid >> 4;   // row base (0..7)

    for (int k0 = 0; k0 < DM; k0 += 16) {
        #pragma unroll
        for (int i = 0; i < 8; i++) {
            int row = ld_r + 8 * i;
            As[ld_d][row] = x[(size_t)Rw[row] * DM + k0 + ld_d];
        }
        #pragma unroll
        for (int i = 0; i < 8; i++) {
            int nn  = ld_r + 8 * i;
            int col = (nn & 1) ? (HID + g0 + (nn >> 1)) : (g0 + (nn >> 1));
            Bs[ld_d][nn] = w_up[((size_t)e * TWO_H + col) * DM + k0 + ld_d];
        }
        __syncthreads();
        #pragma unroll
        for (int k = 0; k < 16; k++) {
            float a[8], b[4];
            #pragma unroll
            for (int i = 0; i < 8; i++) a[i] = As[k][ty * 8 + i];
            #pragma unroll
            for (int j = 0; j < 4; j++) b[j] = Bs[k][tx * 4 + j];
            #pragma unroll
            for (int i = 0; i < 8; i++)
                #pragma unroll
                for (int j = 0; j < 4; j++) acc[i][j] = fmaf(a[i], b[j], acc[i][j]);
        }
        __syncthreads();
    }

    // lora-B add: acc += SCALE * t @ up_b^T
    #pragma unroll
    for (int i = 0; i < 8; i++) {
        int m = ty * 8 + i;
        #pragma unroll
        for (int j = 0; j < 4; j++) {
            int nn = tx * 4 + j;
            float s = 0.f;
            #pragma unroll
            for (int r = 0; r < RR; r++) s = fmaf(Ts[m][r], Ub[nn][r], s);
            acc[i][j] += LSCALE * s;
        }
    }

    // erf-gelu(gate) * up, store act
    #pragma unroll
    for (int i = 0; i < 8; i++) {
        int m = ty * 8 + i;
        if (m0 + m < Me) {
            int p = Pr[m];
            float g1 = acc[i][0], u1 = acc[i][1];
            float g2 = acc[i][2], u2 = acc[i][3];
            float a1 = 0.5f * g1 * (1.f + erff(g1 * 0.70710678118654752f)) * u1;
            float a2 = 0.5f * g2 * (1.f + erff(g2 * 0.70710678118654752f)) * u2;
            g_act[(size_t)p * HID + g0 + 2 * tx]     = a1;
            g_act[(size_t)p * HID + g0 + 2 * tx + 1] = a2;
        }
    }
}

// ================= down GEMM + lora-B + routed weight =================
__global__ __launch_bounds__(128) void down_kernel(const float* __restrict__ w_down,
                                                   const float* __restrict__ down_b,
                                                   const float* __restrict__ tw) {
    int e   = blockIdx.z;
    int off = g_offs[e];
    int Me  = g_offs[e + 1] - off;
    int m0  = blockIdx.y * 64;
    if (m0 >= Me) return;
    int c0 = blockIdx.x * 64;

    __shared__ float As[16][68];
    __shared__ float Bs[16][68];
    __shared__ float Ts[64][16];
    __shared__ float Db[64][17];
    __shared__ int   Pr[64];
    __shared__ float Tw[64];

    int tid = threadIdx.x;
    if (tid < 64) {
        int mm = m0 + tid;
        int p  = g_perm[off + min(mm, Me - 1)];
        Pr[tid] = p;
        Tw[tid] = tw[p];
    }
    __syncthreads();
    for (int i = tid; i < 64 * 16; i += 128) {
        int m = i >> 4, r = i & 15;
        Ts[m][r] = g_tdn[Pr[m] * RR + r];
    }
    for (int i = tid; i < 64 * 16; i += 128) {
        int nn = i >> 4, r = i & 15;
        Db[nn][r] = down_b[((size_t)e * DM + c0 + nn) * RR + r];
    }

    int tx = tid & 15, ty = tid >> 4;
    float acc[8][4];
    #pragma unroll
    for (int i = 0; i < 8; i++)
        #pragma unroll
        for (int j = 0; j < 4; j++) acc[i][j] = 0.f;

    int ld_d = tid & 15;
    int ld_r = tid >> 4;

    for (int k0 = 0; k0 < HID; k0 += 16) {
        #pragma unroll
        for (int i = 0; i < 8; i++) {
            int row = ld_r + 8 * i;
            As[ld_d][row] = g_act[(size_t)Pr[row] * HID + k0 + ld_d];
        }
        #pragma unroll
        for (int i = 0; i < 8; i++) {
            int nn = ld_r + 8 * i;
            Bs[ld_d][nn] = w_down[((size_t)e * DM + c0 + nn) * HID + k0 + ld_d];
        }
        __syncthreads();
        #pragma unroll
        for (int k = 0; k < 16; k++) {
            float a[8], b[4];
            #pragma unroll
            for (int i = 0; i < 8; i++) a[i] = As[k][ty * 8 + i];
            #pragma unroll
            for (int j = 0; j < 4; j++) b[j] = Bs[k][tx * 4 + j];
            #pragma unroll
            for (int i = 0; i < 8; i++)
                #pragma unroll
                for (int j = 0; j < 4; j++) acc[i][j] = fmaf(a[i], b[j], acc[i][j]);
        }
        __syncthreads();
    }

    #pragma unroll
    for (int i = 0; i < 8; i++) {
        int m = ty * 8 + i;
        if (m0 + m < Me) {
            int p = Pr[m];
            float w = Tw[m];
            #pragma unroll
            for (int j = 0; j < 4; j++) {
                int nn = tx * 4 + j;
                float s = 0.f;
                #pragma unroll
                for (int r = 0; r < RR; r++) s = fmaf(Ts[m][r], Db[nn][r], s);
                g_buf[(size_t)p * DM + c0 + nn] = (acc[i][j] + LSCALE * s) * w;
            }
        }
    }
}

// ================= top-K sum (vectorized) =================
__global__ void sum_kernel(float* __restrict__ out) {
    int i = blockIdx.x * blockDim.x + threadIdx.x;   // float4 index
    if (i < N_TOK * DM / 4) {
        int n = i / (DM / 4);
        int d = i % (DM / 4);
        const float4* a = (const float4*)(g_buf + (size_t)(2 * n) * DM);
        const float4* b = (const float4*)(g_buf + (size_t)(2 * n + 1) * DM);
        float4 av = a[d], bv = b[d];
        float4 r;
        r.x = av.x + bv.x;
        r.y = av.y + bv.y;
        r.z = av.z + bv.z;
        r.w = av.w + bv.w;
        ((float4*)out)[i] = r;
    }
}

// ================= launch =================
extern "C" void kernel_launch(void* const* d_in, const int* in_sizes, int n_in,
                              void* d_out, int out_size) {
    const float* x    = (const float*)d_in[0];
    const float* twt  = (const float*)d_in[1];
    const int*   ids  = (const int*)d_in[2];
    const float* w_up = (const float*)d_in[3];
    const float* w_dn = (const float*)d_in[4];
    const float* up_a = (const float*)d_in[5];
    const float* up_b = (const float*)d_in[6];
    const float* dn_a = (const float*)d_in[7];
    const float* dn_b = (const float*)d_in[8];
    float* out = (float*)d_out;

    route_kernel<<<1, 256>>>(ids);
    tup_kernel<<<NP, 128>>>(x, up_a, ids);
    // grid: (H/32 gate-col tiles, max m-tiles, experts)
    up_kernel<<<dim3(HID / 32, NP / 64, NE), 128>>>(x, w_up, up_b);
    tdn_kernel<<<NP, 128>>>(dn_a, ids);
    down_kernel<<<dim3(DM / 64, NP / 64, NE), 128>>>(w_dn, dn_b, twt);
    sum_kernel<<<(N_TOK * DM / 4 + 255) / 256, 256>>>(out);
}

// round 6
// speedup vs baseline: 2.5245x; 2.5245x over previous
#include <cuda_runtime.h>
#include <cuda_bf16.h>
#include <math.h>

// Problem constants (fixed shapes per reference setup_inputs)
#define N_TOK 1024
#define TOPK  2
#define NP    (N_TOK * TOPK)   // 2048 (token,k) pairs
#define NE    16
#define HID   1024
#define TWO_H 2048
#define DM    2048
#define RR    16
#define LSCALE 0.25f

// ---------------- device scratch (no allocations allowed) ----------------
__device__ int   g_perm[NP];
__device__ int   g_offs[NE + 1];
__device__ float g_tup[NP * RR];
__device__ float g_tdn[NP * RR];
__device__ float g_act[(size_t)NP * HID];
__device__ float g_buf[(size_t)NP * DM];
// bf16 hi/lo splits, packed 8 bf16 per uint4
__device__ uint4 g_xhi[(size_t)N_TOK * DM / 8];
__device__ uint4 g_xlo[(size_t)N_TOK * DM / 8];
__device__ uint4 g_ahi[(size_t)NP * HID / 8];
__device__ uint4 g_alo[(size_t)NP * HID / 8];

// ---------------- helpers ----------------
__device__ __forceinline__ unsigned smem_u32(const void* p) {
    unsigned a;
    asm("{ .reg .u64 t; cvta.to.shared.u64 t, %1; cvt.u32.u64 %0, t; }" : "=r"(a) : "l"(p));
    return a;
}
__device__ __forceinline__ void ldsm4(unsigned& r0, unsigned& r1, unsigned& r2, unsigned& r3,
                                      unsigned addr) {
    asm volatile("ldmatrix.sync.aligned.m8n8.x4.shared.b16 {%0,%1,%2,%3}, [%4];"
                 : "=r"(r0), "=r"(r1), "=r"(r2), "=r"(r3) : "r"(addr));
}
__device__ __forceinline__ void ldsm2(unsigned& r0, unsigned& r1, unsigned addr) {
    asm volatile("ldmatrix.sync.aligned.m8n8.x2.shared.b16 {%0,%1}, [%2];"
                 : "=r"(r0), "=r"(r1) : "r"(addr));
}
__device__ __forceinline__ void mma16816(float* c, const unsigned* a, const unsigned* b) {
    asm volatile("mma.sync.aligned.m16n8k16.row.col.f32.bf16.bf16.f32 "
                 "{%0,%1,%2,%3},{%4,%5,%6,%7},{%8,%9},{%0,%1,%2,%3};"
                 : "+f"(c[0]), "+f"(c[1]), "+f"(c[2]), "+f"(c[3])
                 : "r"(a[0]), "r"(a[1]), "r"(a[2]), "r"(a[3]), "r"(b[0]), "r"(b[1]));
}
// bf16 hi/lo split of two floats, packed into bf16x2 words
__device__ __forceinline__ void split2(float x, float y, unsigned& hi, unsigned& lo) {
    __nv_bfloat16 hx = __float2bfloat16(x), hy = __float2bfloat16(y);
    float rx = x - __bfloat162float(hx), ry = y - __bfloat162float(hy);
    __nv_bfloat16 lx = __float2bfloat16(rx), ly = __float2bfloat16(ry);
    hi = ((unsigned)__bfloat16_as_ushort(hy) << 16) | (unsigned)__bfloat16_as_ushort(hx);
    lo = ((unsigned)__bfloat16_as_ushort(ly) << 16) | (unsigned)__bfloat16_as_ushort(lx);
}

// smem layout (bytes). A rows: 32 bf16 padded to 40 (80B stride, conflict-free ldmatrix)
#define SA_STRIDE 80
#define SM_AHI 0
#define SM_ALO 10240
#define SM_BHI 20480
#define SM_BLO 25600
#define SM_TS  30720          // 128*17 floats
#define SM_LB  39424          // 64*16 floats (Ub / Db)
#define SM_PR  43520          // 128 ints
#define SM_AUX 44032          // 128 ints/floats
#define SM_SZ  44544

// ================= routing =================
__global__ void route_kernel(const int* __restrict__ ids) {
    __shared__ int cnt[NE];
    __shared__ int base[NE + 1];
    __shared__ int cur[NE];
    int t = threadIdx.x;
    if (t < NE) cnt[t] = 0;
    __syncthreads();
    for (int p = t; p < NP; p += blockDim.x) atomicAdd(&cnt[ids[p]], 1);
    __syncthreads();
    if (t == 0) {
        int s = 0;
        for (int e = 0; e < NE; e++) { base[e] = s; s += cnt[e]; }
        base[NE] = s;
    }
    __syncthreads();
    if (t <= NE) g_offs[t] = base[t];
    if (t < NE)  cur[t] = base[t];
    __syncthreads();
    for (int p = t; p < NP; p += blockDim.x) {
        int pos = atomicAdd(&cur[ids[p]], 1);
        g_perm[pos] = p;
    }
}

// ================= x -> bf16 hi/lo split =================
__global__ void xconv_kernel(const float* __restrict__ x) {
    int i = blockIdx.x * blockDim.x + threadIdx.x;   // uint4 index
    if (i >= N_TOK * DM / 8) return;
    const float4* src = (const float4*)x + (size_t)i * 2;
    float4 v0 = src[0], v1 = src[1];
    uint4 h, l;
    split2(v0.x, v0.y, h.x, l.x);
    split2(v0.z, v0.w, h.y, l.y);
    split2(v1.x, v1.y, h.z, l.z);
    split2(v1.z, v1.w, h.w, l.w);
    g_xhi[i] = h;
    g_xlo[i] = l;
}

// ================= lora-A kernels =================
__global__ void tup_kernel(const float* __restrict__ x,
                           const float* __restrict__ up_a,
                           const int*   __restrict__ ids) {
    int p = blockIdx.x;
    int e = ids[p];
    const float4* xr = (const float4*)(x + (size_t)(p >> 1) * DM);
    int w = threadIdx.x >> 5, lane = threadIdx.x & 31;
    for (int r = w; r < RR; r += 4) {
        const float4* ar = (const float4*)(up_a + ((size_t)e * RR + r) * DM);
        float s = 0.f;
        for (int d = lane; d < DM / 4; d += 32) {
            float4 xv = xr[d], av = ar[d];
            s = fmaf(xv.x, av.x, s); s = fmaf(xv.y, av.y, s);
            s = fmaf(xv.z, av.z, s); s = fmaf(xv.w, av.w, s);
        }
        #pragma unroll
        for (int o = 16; o; o >>= 1) s += __shfl_xor_sync(0xffffffffu, s, o);
        if (lane == 0) g_tup[p * RR + r] = s;
    }
}

__global__ void tdn_kernel(const float* __restrict__ down_a,
                           const int*   __restrict__ ids) {
    int p = blockIdx.x;
    int e = ids[p];
    const float4* xr = (const float4*)(g_act + (size_t)p * HID);
    int w = threadIdx.x >> 5, lane = threadIdx.x & 31;
    for (int r = w; r < RR; r += 4) {
        const float4* ar = (const float4*)(down_a + ((size_t)e * RR + r) * HID);
        float s = 0.f;
        for (int d = lane; d < HID / 4; d += 32) {
            float4 xv = xr[d], av = ar[d];
            s = fmaf(xv.x, av.x, s); s = fmaf(xv.y, av.y, s);
            s = fmaf(xv.z, av.z, s); s = fmaf(xv.w, av.w, s);
        }
        #pragma unroll
        for (int o = 16; o; o >>= 1) s += __shfl_xor_sync(0xffffffffu, s, o);
        if (lane == 0) g_tdn[p * RR + r] = s;
    }
}

// ================= up GEMM (HMMA) + lora-B + erf-gelu-mul =================
// BM=128 pairs x BN=64 interleaved (gate,up) cols, BK=32, 8 warps (4M x 2N).
__global__ __launch_bounds__(256) void up_mma_kernel(const float* __restrict__ w_up,
                                                     const float* __restrict__ up_b) {
    __shared__ __align__(16) char smem[SM_SZ];
    unsigned sb = smem_u32(smem);
    int tid = threadIdx.x, lane = tid & 31, wid = tid >> 5;
    int warpM = wid & 3, warpN = wid >> 2;
    int e   = blockIdx.z;
    int off = g_offs[e], Me = g_offs[e + 1] - off;
    int m0  = blockIdx.y * 128;
    if (m0 >= Me) return;
    int g_h = blockIdx.x * 32;   // h-base; CTA covers interleaved cols 2*g_h .. +63

    int*   Pr = (int*)(smem + SM_PR);
    int*   Rw = (int*)(smem + SM_AUX);
    float* Ts = (float*)(smem + SM_TS);
    float* Ub = (float*)(smem + SM_LB);

    if (tid < 128) {
        int mm = m0 + tid;
        int p  = g_perm[off + min(mm, Me - 1)];
        Pr[tid] = p;
        Rw[tid] = p >> 1;
    }
    __syncthreads();
    for (int i = tid; i < 128 * 16; i += 256) {
        int m = i >> 4, r = i & 15;
        Ts[m * 17 + r] = g_tup[Pr[m] * RR + r];
    }
    for (int i = tid; i < 64 * 16; i += 256) {
        int nn = i >> 4, r = i & 15;
        int col = (nn & 1) ? (HID + g_h + (nn >> 1)) : (g_h + (nn >> 1));
        Ub[nn * 16 + r] = up_b[((size_t)e * TWO_H + col) * RR + r];
    }

    // per-thread load indices
    int arow = tid >> 1, aseg = tid & 1;              // A: 2 items/thread => rows via it*128
    int brow = tid >> 3, bseg = tid & 7;              // B: row 0..31 (+32 on it=1), seg 0..7
    float acc[2][4][4];
    #pragma unroll
    for (int a = 0; a < 2; a++)
        #pragma unroll
        for (int b = 0; b < 4; b++)
            #pragma unroll
            for (int q = 0; q < 4; q++) acc[a][b][q] = 0.f;

    uint4 pah[2], pal[2];
    float4 pb[2];

    const int NCH = DM / 32;   // 64
    // ---- prefetch chunk 0 ----
    #pragma unroll
    for (int it = 0; it < 2; it++) {
        int item = it * 256 + tid;
        int row = item >> 2, seg = item & 3;
        size_t gi = (size_t)Rw[row] * (DM / 8) + seg;
        pah[it] = g_xhi[gi];
        pal[it] = g_xlo[gi];
    }
    #pragma unroll
    for (int it = 0; it < 2; it++) {
        int row = (it * 256 + tid) >> 3;
        int col = (row & 1) ? (HID + g_h + (row >> 1)) : (g_h + (row >> 1));
        pb[it] = *(const float4*)(w_up + ((size_t)e * TWO_H + col) * DM + bseg * 4);
    }
    // ---- store chunk 0 ----
    #pragma unroll
    for (int it = 0; it < 2; it++) {
        int item = it * 256 + tid;
        int row = item >> 2, seg = item & 3;
        unsigned so = row * SA_STRIDE + seg * 16;
        *(uint4*)(smem + SM_AHI + so) = pah[it];
        *(uint4*)(smem + SM_ALO + so) = pal[it];
    }
    #pragma unroll
    for (int it = 0; it < 2; it++) {
        int row = (it * 256 + tid) >> 3;
        uint2 h, l;
        split2(pb[it].x, pb[it].y, h.x, l.x);
        split2(pb[it].z, pb[it].w, h.y, l.y);
        unsigned so = row * SA_STRIDE + bseg * 8;
        *(uint2*)(smem + SM_BHI + so) = h;
        *(uint2*)(smem + SM_BLO + so) = l;
    }
    __syncthreads();

    unsigned aoff = (lane & 15) * SA_STRIDE + (lane >> 4) * 16;
    unsigned boff = (lane & 7) * SA_STRIDE + ((lane >> 3) & 1) * 16;
    unsigned abase = sb + warpM * 32 * SA_STRIDE + aoff;
    unsigned bbase = sb + warpN * 32 * SA_STRIDE + boff;

    for (int c = 0; c < NCH; c++) {
        // prefetch next chunk
        if (c + 1 < NCH) {
            int k0 = (c + 1) * 32;
            #pragma unroll
            for (int it = 0; it < 2; it++) {
                int item = it * 256 + tid;
                int row = item >> 2, seg = item & 3;
                size_t gi = (size_t)Rw[row] * (DM / 8) + (k0 >> 3) + seg;
                pah[it] = g_xhi[gi];
                pal[it] = g_xlo[gi];
            }
            #pragma unroll
            for (int it = 0; it < 2; it++) {
                int row = (it * 256 + tid) >> 3;
                int col = (row & 1) ? (HID + g_h + (row >> 1)) : (g_h + (row >> 1));
                pb[it] = *(const float4*)(w_up + ((size_t)e * TWO_H + col) * DM + k0 + bseg * 4);
            }
        }
        // compute current chunk
        #pragma unroll
        for (int ks = 0; ks < 2; ks++) {
            unsigned bh[8], bl[8];
            #pragma unroll
            for (int nt = 0; nt < 4; nt++) {
                ldsm2(bh[2*nt], bh[2*nt+1], bbase + SM_BHI + nt * 8 * SA_STRIDE + ks * 32);
                ldsm2(bl[2*nt], bl[2*nt+1], bbase + SM_BLO + nt * 8 * SA_STRIDE + ks * 32);
            }
            #pragma unroll
            for (int mt = 0; mt < 2; mt++) {
                unsigned ah[4], al[4];
                ldsm4(ah[0], ah[1], ah[2], ah[3], abase + SM_AHI + mt * 16 * SA_STRIDE + ks * 32);
                ldsm4(al[0], al[1], al[2], al[3], abase + SM_ALO + mt * 16 * SA_STRIDE + ks * 32);
                #pragma unroll
                for (int nt = 0; nt < 4; nt++) {
                    mma16816(acc[mt][nt], ah, &bh[2*nt]);
                    mma16816(acc[mt][nt], ah, &bl[2*nt]);
                    mma16816(acc[mt][nt], al, &bh[2*nt]);
                }
            }
        }
        __syncthreads();
        if (c + 1 < NCH) {
            #pragma unroll
            for (int it = 0; it < 2; it++) {
                int item = it * 256 + tid;
                int row = item >> 2, seg = item & 3;
                unsigned so = row * SA_STRIDE + seg * 16;
                *(uint4*)(smem + SM_AHI + so) = pah[it];
                *(uint4*)(smem + SM_ALO + so) = pal[it];
            }
            #pragma unroll
            for (int it = 0; it < 2; it++) {
                int row = (it * 256 + tid) >> 3;
                uint2 h, l;
                split2(pb[it].x, pb[it].y, h.x, l.x);
                split2(pb[it].z, pb[it].w, h.y, l.y);
                unsigned so = row * SA_STRIDE + bseg * 8;
                *(uint2*)(smem + SM_BHI + so) = h;
                *(uint2*)(smem + SM_BLO + so) = l;
            }
            __syncthreads();
        }
    }

    // epilogue: lora-B add + erf-gelu-mul, write act (fp32 + bf16 hi/lo)
    #pragma unroll
    for (int mt = 0; mt < 2; mt++) {
        #pragma unroll
        for (int half = 0; half < 2; half++) {
            int mrow = warpM * 32 + mt * 16 + (lane >> 2) + half * 8;
            if (m0 + mrow >= Me) continue;
            int p = Pr[mrow];
            const float* ts = Ts + mrow * 17;
            #pragma unroll
            for (int nt = 0; nt < 4; nt++) {
                int nn = warpN * 32 + nt * 8 + (lane & 3) * 2;
                float sg = 0.f, su = 0.f;
                const float* ug = Ub + nn * 16;
                const float* uu = Ub + (nn + 1) * 16;
                #pragma unroll
                for (int r = 0; r < RR; r++) {
                    sg = fmaf(ts[r], ug[r], sg);
                    su = fmaf(ts[r], uu[r], su);
                }
                float g = acc[mt][nt][half * 2]     + LSCALE * sg;
                float u = acc[mt][nt][half * 2 + 1] + LSCALE * su;
                float av = 0.5f * g * (1.f + erff(g * 0.70710678118654752f)) * u;
                int h = g_h + (nn >> 1);
                g_act[(size_t)p * HID + h] = av;
                unsigned hi, lo;
                split2(av, 0.f, hi, lo);
                ((unsigned short*)g_ahi)[(size_t)p * HID + h] = (unsigned short)(hi & 0xFFFF);
                ((unsigned short*)g_alo)[(size_t)p * HID + h] = (unsigned short)(lo & 0xFFFF);
            }
        }
    }
}

// ================= down GEMM (HMMA) + lora-B + routed weight =================
__global__ __launch_bounds__(256) void down_mma_kernel(const float* __restrict__ w_down,
                                                       const float* __restrict__ down_b,
                                                       const float* __restrict__ tw) {
    __shared__ __align__(16) char smem[SM_SZ];
    unsigned sb = smem_u32(smem);
    int tid = threadIdx.x, lane = tid & 31, wid = tid >> 5;
    int warpM = wid & 3, warpN = wid >> 2;
    int e   = blockIdx.z;
    int off = g_offs[e], Me = g_offs[e + 1] - off;
    int m0  = blockIdx.y * 128;
    if (m0 >= Me) return;
    int c0 = blockIdx.x * 64;

    int*   Pr = (int*)(smem + SM_PR);
    float* Tw = (float*)(smem + SM_AUX);
    float* Ts = (float*)(smem + SM_TS);
    float* Db = (float*)(smem + SM_LB);

    if (tid < 128) {
        int mm = m0 + tid;
        int p  = g_perm[off + min(mm, Me - 1)];
        Pr[tid] = p;
        Tw[tid] = tw[p];
    }
    __syncthreads();
    for (int i = tid; i < 128 * 16; i += 256) {
        int m = i >> 4, r = i & 15;
        Ts[m * 17 + r] = g_tdn[Pr[m] * RR + r];
    }
    for (int i = tid; i < 64 * 16; i += 256) {
        int nn = i >> 4, r = i & 15;
        Db[nn * 16 + r] = down_b[((size_t)e * DM + c0 + nn) * RR + r];
    }

    int bseg = tid & 7;
    float acc[2][4][4];
    #pragma unroll
    for (int a = 0; a < 2; a++)
        #pragma unroll
        for (int b = 0; b < 4; b++)
            #pragma unroll
            for (int q = 0; q < 4; q++) acc[a][b][q] = 0.f;

    uint4 pah[2], pal[2];
    float4 pb[2];

    const int NCH = HID / 32;   // 32
    #pragma unroll
    for (int it = 0; it < 2; it++) {
        int item = it * 256 + tid;
        int row = item >> 2, seg = item & 3;
        size_t gi = (size_t)Pr[row] * (HID / 8) + seg;
        pah[it] = g_ahi[gi];
        pal[it] = g_alo[gi];
    }
    #pragma unroll
    for (int it = 0; it < 2; it++) {
        int row = (it * 256 + tid) >> 3;
        pb[it] = *(const float4*)(w_down + ((size_t)e * DM + c0 + row) * HID + bseg * 4);
    }
    #pragma unroll
    for (int it = 0; it < 2; it++) {
        int item = it * 256 + tid;
        int row = item >> 2, seg = item & 3;
        unsigned so = row * SA_STRIDE + seg * 16;
        *(uint4*)(smem + SM_AHI + so) = pah[it];
        *(uint4*)(smem + SM_ALO + so) = pal[it];
    }
    #pragma unroll
    for (int it = 0; it < 2; it++) {
        int row = (it * 256 + tid) >> 3;
        uint2 h, l;
        split2(pb[it].x, pb[it].y, h.x, l.x);
        split2(pb[it].z, pb[it].w, h.y, l.y);
        unsigned so = row * SA_STRIDE + bseg * 8;
        *(uint2*)(smem + SM_BHI + so) = h;
        *(uint2*)(smem + SM_BLO + so) = l;
    }
    __syncthreads();

    unsigned aoff = (lane & 15) * SA_STRIDE + (lane >> 4) * 16;
    unsigned boff = (lane & 7) * SA_STRIDE + ((lane >> 3) & 1) * 16;
    unsigned abase = sb + warpM * 32 * SA_STRIDE + aoff;
    unsigned bbase = sb + warpN * 32 * SA_STRIDE + boff;

    for (int c = 0; c < NCH; c++) {
        if (c + 1 < NCH) {
            int k0 = (c + 1) * 32;
            #pragma unroll
            for (int it = 0; it < 2; it++) {
                int item = it * 256 + tid;
                int row = item >> 2, seg = item & 3;
                size_t gi = (size_t)Pr[row] * (HID / 8) + (k0 >> 3) + seg;
                pah[it] = g_ahi[gi];
                pal[it] = g_alo[gi];
            }
            #pragma unroll
            for (int it = 0; it < 2; it++) {
                int row = (it * 256 + tid) >> 3;
                pb[it] = *(const float4*)(w_down + ((size_t)e * DM + c0 + row) * HID + k0 + bseg * 4);
            }
        }
        #pragma unroll
        for (int ks = 0; ks < 2; ks++) {
            unsigned bh[8], bl[8];
            #pragma unroll
            for (int nt = 0; nt < 4; nt++) {
                ldsm2(bh[2*nt], bh[2*nt+1], bbase + SM_BHI + nt * 8 * SA_STRIDE + ks * 32);
                ldsm2(bl[2*nt], bl[2*nt+1], bbase + SM_BLO + nt * 8 * SA_STRIDE + ks * 32);
            }
            #pragma unroll
            for (int mt = 0; mt < 2; mt++) {
                unsigned ah[4], al[4];
                ldsm4(ah[0], ah[1], ah[2], ah[3], abase + SM_AHI + mt * 16 * SA_STRIDE + ks * 32);
                ldsm4(al[0], al[1], al[2], al[3], abase + SM_ALO + mt * 16 * SA_STRIDE + ks * 32);
                #pragma unroll
                for (int nt = 0; nt < 4; nt++) {
                    mma16816(acc[mt][nt], ah, &bh[2*nt]);
                    mma16816(acc[mt][nt], ah, &bl[2*nt]);
                    mma16816(acc[mt][nt], al, &bh[2*nt]);
                }
            }
        }
        __syncthreads();
        if (c + 1 < NCH) {
            #pragma unroll
            for (int it = 0; it < 2; it++) {
                int item = it * 256 + tid;
                int row = item >> 2, seg = item & 3;
                unsigned so = row * SA_STRIDE + seg * 16;
                *(uint4*)(smem + SM_AHI + so) = pah[it];
                *(uint4*)(smem + SM_ALO + so) = pal[it];
            }
            #pragma unroll
            for (int it = 0; it < 2; it++) {
                int row = (it * 256 + tid) >> 3;
                uint2 h, l;
                split2(pb[it].x, pb[it].y, h.x, l.x);
                split2(pb[it].z, pb[it].w, h.y, l.y);
                unsigned so = row * SA_STRIDE + bseg * 8;
                *(uint2*)(smem + SM_BHI + so) = h;
                *(uint2*)(smem + SM_BLO + so) = l;
            }
            __syncthreads();
        }
    }

    // epilogue: lora-B + routed weight
    #pragma unroll
    for (int mt = 0; mt < 2; mt++) {
        #pragma unroll
        for (int half = 0; half < 2; half++) {
            int mrow = warpM * 32 + mt * 16 + (lane >> 2) + half * 8;
            if (m0 + mrow >= Me) continue;
            int p = Pr[mrow];
            float w = Tw[mrow];
            const float* ts = Ts + mrow * 17;
            #pragma unroll
            for (int nt = 0; nt < 4; nt++) {
                int nn = warpN * 32 + nt * 8 + (lane & 3) * 2;
                float s0 = 0.f, s1 = 0.f;
                const float* d0 = Db + nn * 16;
                const float* d1 = Db + (nn + 1) * 16;
                #pragma unroll
                for (int r = 0; r < RR; r++) {
                    s0 = fmaf(ts[r], d0[r], s0);
                    s1 = fmaf(ts[r], d1[r], s1);
                }
                float2 o;
                o.x = (acc[mt][nt][half * 2]     + LSCALE * s0) * w;
                o.y = (acc[mt][nt][half * 2 + 1] + LSCALE * s1) * w;
                *(float2*)(g_buf + (size_t)p * DM + c0 + nn) = o;
            }
        }
    }
}

// ================= top-K sum =================
__global__ void sum_kernel(float* __restrict__ out) {
    int i = blockIdx.x * blockDim.x + threadIdx.x;
    if (i < N_TOK * DM / 4) {
        int n = i / (DM / 4);
        int d = i % (DM / 4);
        const float4* a = (const float4*)(g_buf + (size_t)(2 * n) * DM);
        const float4* b = (const float4*)(g_buf + (size_t)(2 * n + 1) * DM);
        float4 av = a[d], bv = b[d];
        float4 r;
        r.x = av.x + bv.x; r.y = av.y + bv.y;
        r.z = av.z + bv.z; r.w = av.w + bv.w;
        ((float4*)out)[i] = r;
    }
}

// ================= launch =================
extern "C" void kernel_launch(void* const* d_in, const int* in_sizes, int n_in,
                              void* d_out, int out_size) {
    const float* x    = (const float*)d_in[0];
    const float* twt  = (const float*)d_in[1];
    const int*   ids  = (const int*)d_in[2];
    const float* w_up = (const float*)d_in[3];
    const float* w_dn = (const float*)d_in[4];
    const float* up_a = (const float*)d_in[5];
    const float* up_b = (const float*)d_in[6];
    const float* dn_a = (const float*)d_in[7];
    const float* dn_b = (const float*)d_in[8];
    float* out = (float*)d_out;

    route_kernel<<<1, 256>>>(ids);
    xconv_kernel<<<(N_TOK * DM / 8 + 255) / 256, 256>>>(x);
    tup_kernel<<<NP, 128>>>(x, up_a, ids);
    // up: (2H/64 col tiles using h-base of 32, m-tiles, experts)
    up_mma_kernel<<<dim3(HID / 32, NP / 128, NE), 256>>>(w_up, up_b);
    tdn_kernel<<<NP, 128>>>(dn_a, ids);
    down_mma_kernel<<<dim3(DM / 64, NP / 128, NE), 256>>>(w_dn, dn_b, twt);
    sum_kernel<<<(N_TOK * DM / 4 + 255) / 256, 256>>>(out);
}